// round 2
// baseline (speedup 1.0000x reference)
#include <cuda_runtime.h>
#include <cstdint>

#define NH   12
#define DHD  64
#define NSEQ 1024
#define DM   768
#define NTB  16
#define NS   16384   // NTB * NSEQ tokens

// ---------------------------------------------------------------------------
// Scratch (static device globals; no runtime allocation allowed)
// ---------------------------------------------------------------------------
__device__ float g_q[(size_t)NTB * NH * NSEQ * DHD];   // head-split q
__device__ float g_k[(size_t)NTB * NH * NSEQ * DHD];   // head-split k
__device__ float g_v[(size_t)NTB * NH * NSEQ * DHD];   // head-split v
__device__ float g_ctx[(size_t)NS * DM];               // merged attention output

// ---------------------------------------------------------------------------
// Helpers
// ---------------------------------------------------------------------------
__device__ __forceinline__ float f2tf(float x) {
    unsigned u;
    asm("cvt.rna.tf32.f32 %0, %1;" : "=r"(u) : "f"(x));
    return __uint_as_float(u);
}

__device__ __forceinline__ void mma8(float& c0, float& c1, float& c2, float& c3,
                                     unsigned a0, unsigned a1, unsigned a2, unsigned a3,
                                     unsigned b0, unsigned b1) {
    asm volatile(
        "mma.sync.aligned.m16n8k8.row.col.f32.tf32.tf32.f32 "
        "{%0,%1,%2,%3},{%4,%5,%6,%7},{%8,%9},{%0,%1,%2,%3};"
        : "+f"(c0), "+f"(c1), "+f"(c2), "+f"(c3)
        : "r"(a0), "r"(a1), "r"(a2), "r"(a3), "r"(b0), "r"(b1));
}

// ---------------------------------------------------------------------------
// GEMM: out[s, c] = sum_k A[s, k] * W[c, k] + bias[c]
// CTA tile 128x128, BK=32, 256 threads (8 warps as 4(m) x 2(n), warp 32x64).
// If dsthead != nullptr, write into head-split layout [(tb*NH+h), n, d].
// ---------------------------------------------------------------------------
__device__ __forceinline__ void gemm_body(const float* __restrict__ Ap,
                                          const float* __restrict__ W,
                                          const float* __restrict__ bias,
                                          float* __restrict__ dsthead,
                                          float* __restrict__ dstflat) {
    __shared__ float As[128][36];   // pad 4 -> conflict-free frag loads
    __shared__ float Bs[128][36];

    const int tid  = threadIdx.x;
    const int lane = tid & 31, wid = tid >> 5;
    const int wm = (wid & 3) * 32;          // warp m-offset
    const int wn = (wid >> 2) * 64;         // warp n-offset
    const int row0 = blockIdx.x * 128, col0 = blockIdx.y * 128;
    const int lr = lane >> 2, lc = lane & 3;

    float acc[2][8][4];
#pragma unroll
    for (int i = 0; i < 2; i++)
#pragma unroll
        for (int j = 0; j < 8; j++)
#pragma unroll
            for (int e = 0; e < 4; e++) acc[i][j][e] = 0.f;

    const int ldr = tid >> 3;               // 0..31
    const int ldc = (tid & 7) << 2;         // 0,4,..,28

    for (int kk = 0; kk < DM; kk += 32) {
#pragma unroll
        for (int i = 0; i < 4; i++) {
            const int rr = ldr + i * 32;
            float4 av = *reinterpret_cast<const float4*>(Ap + (size_t)(row0 + rr) * DM + kk + ldc);
            As[rr][ldc + 0] = f2tf(av.x);
            As[rr][ldc + 1] = f2tf(av.y);
            As[rr][ldc + 2] = f2tf(av.z);
            As[rr][ldc + 3] = f2tf(av.w);
            float4 wv = *reinterpret_cast<const float4*>(W + (size_t)(col0 + rr) * DM + kk + ldc);
            Bs[rr][ldc + 0] = f2tf(wv.x);
            Bs[rr][ldc + 1] = f2tf(wv.y);
            Bs[rr][ldc + 2] = f2tf(wv.z);
            Bs[rr][ldc + 3] = f2tf(wv.w);
        }
        __syncthreads();

#pragma unroll
        for (int ks = 0; ks < 4; ks++) {
            const int k0 = ks * 8;
            unsigned af[2][4];
#pragma unroll
            for (int mi = 0; mi < 2; mi++) {
                const int r = wm + mi * 16 + lr;
                af[mi][0] = __float_as_uint(As[r][k0 + lc]);
                af[mi][1] = __float_as_uint(As[r + 8][k0 + lc]);
                af[mi][2] = __float_as_uint(As[r][k0 + 4 + lc]);
                af[mi][3] = __float_as_uint(As[r + 8][k0 + 4 + lc]);
            }
            unsigned bf[8][2];
#pragma unroll
            for (int ni = 0; ni < 8; ni++) {
                const int r = wn + ni * 8 + lr;
                bf[ni][0] = __float_as_uint(Bs[r][k0 + lc]);
                bf[ni][1] = __float_as_uint(Bs[r][k0 + 4 + lc]);
            }
#pragma unroll
            for (int mi = 0; mi < 2; mi++)
#pragma unroll
                for (int ni = 0; ni < 8; ni++)
                    mma8(acc[mi][ni][0], acc[mi][ni][1], acc[mi][ni][2], acc[mi][ni][3],
                         af[mi][0], af[mi][1], af[mi][2], af[mi][3],
                         bf[ni][0], bf[ni][1]);
        }
        __syncthreads();
    }

    // epilogue
#pragma unroll
    for (int mi = 0; mi < 2; mi++)
#pragma unroll
        for (int ni = 0; ni < 8; ni++)
#pragma unroll
            for (int e = 0; e < 4; e++) {
                const int gr = row0 + wm + mi * 16 + lr + ((e >> 1) << 3);
                const int gc = col0 + wn + ni * 8 + (lc << 1) + (e & 1);
                const float v = acc[mi][ni][e] + bias[gc];
                if (dsthead) {
                    const int tb = gr >> 10, n = gr & 1023;
                    const int h = gc >> 6, d = gc & 63;
                    dsthead[(((size_t)(tb * NH + h)) * NSEQ + n) * DHD + d] = v;
                } else {
                    dstflat[(size_t)gr * DM + gc] = v;
                }
            }
}

__global__ __launch_bounds__(256) void gemm_qkv_k(const float* __restrict__ x,
                                                  const float* __restrict__ Wq, const float* __restrict__ bq,
                                                  const float* __restrict__ Wk, const float* __restrict__ bk,
                                                  const float* __restrict__ Wv, const float* __restrict__ bv) {
    const int m = blockIdx.z;
    const float* W = (m == 0) ? Wq : (m == 1) ? Wk : Wv;
    const float* b = (m == 0) ? bq : (m == 1) ? bk : bv;
    float* dst = (m == 0) ? g_q : (m == 1) ? g_k : g_v;
    gemm_body(x, W, b, dst, nullptr);
}

__global__ __launch_bounds__(256) void gemm_out_k(const float* __restrict__ Wo,
                                                  const float* __restrict__ bo,
                                                  float* __restrict__ out) {
    gemm_body(g_ctx, Wo, bo, nullptr, out);
}

// ---------------------------------------------------------------------------
// Attention: per (tb,h), 1024x1024x64. CTA = 128 q-rows, streams 32-key blocks.
// P = relu(q k^T / 8); ctx = (P @ v) / (rowsum(P) + eps).
// 128 threads = 4 warps, each warp owns 32 q-rows (2 m-frags).
// ---------------------------------------------------------------------------
#define QS_STR 68
#define KS_STR 68
#define VS_STR 72   // 72 % 32 == 8 -> conflict-free B-frag loads (k-major rows)
#define PS_STR 36
#define SMEM_F (128 * QS_STR + 32 * KS_STR + 32 * VS_STR + 4 * 32 * PS_STR)

__global__ __launch_bounds__(128) void attn_k() {
    extern __shared__ float sm[];
    float* Qs = sm;                        // [128][68]
    float* Ks = Qs + 128 * QS_STR;         // [32][68]  rows = key, cols = dh
    float* Vs = Ks + 32 * KS_STR;          // [32][72]  rows = key, cols = dh
    float* Ps = Vs + 32 * VS_STR;          // [4][32][36] per-warp P tile

    const int tid = threadIdx.x, lane = tid & 31, wid = tid >> 5;
    const int lr = lane >> 2, lc = lane & 3;
    const int qb = blockIdx.x, tbh = blockIdx.y;
    const float* qp = g_q + (size_t)tbh * NSEQ * DHD + (size_t)qb * 128 * DHD;
    const float* kp = g_k + (size_t)tbh * NSEQ * DHD;
    const float* vp = g_v + (size_t)tbh * NSEQ * DHD;

    // load Q block (scale by 1/8 folded in; relu(s/8) == relu(s)/8 so this is exact)
    {
        const int r = tid >> 4;
        const int c4 = (tid & 15) << 2;
#pragma unroll
        for (int i = 0; i < 16; i++) {
            const int rr = r + i * 8;
            float4 v4 = *reinterpret_cast<const float4*>(qp + rr * DHD + c4);
            float* q = Qs + rr * QS_STR + c4;
            q[0] = f2tf(v4.x * 0.125f);
            q[1] = f2tf(v4.y * 0.125f);
            q[2] = f2tf(v4.z * 0.125f);
            q[3] = f2tf(v4.w * 0.125f);
        }
    }
    __syncthreads();

    float ctx[2][8][4];
#pragma unroll
    for (int i = 0; i < 2; i++)
#pragma unroll
        for (int j = 0; j < 8; j++)
#pragma unroll
            for (int e = 0; e < 4; e++) ctx[i][j][e] = 0.f;
    float rs[2][2] = {{0.f, 0.f}, {0.f, 0.f}};

    const int wm = wid * 32;
    float* Pw = Ps + wid * 32 * PS_STR;

    for (int kvb = 0; kvb < NSEQ / 32; kvb++) {
        {   // load K,V 32x64 tiles
            const int r = tid >> 4;
            const int c4 = (tid & 15) << 2;
            const float* kb = kp + (size_t)kvb * 32 * DHD;
            const float* vb = vp + (size_t)kvb * 32 * DHD;
#pragma unroll
            for (int i = 0; i < 4; i++) {
                const int rr = r + i * 8;
                float4 k4 = *reinterpret_cast<const float4*>(kb + rr * DHD + c4);
                float* kd = Ks + rr * KS_STR + c4;
                kd[0] = f2tf(k4.x); kd[1] = f2tf(k4.y); kd[2] = f2tf(k4.z); kd[3] = f2tf(k4.w);
                float4 v4 = *reinterpret_cast<const float4*>(vb + rr * DHD + c4);
                float* vd = Vs + rr * VS_STR + c4;
                vd[0] = f2tf(v4.x); vd[1] = f2tf(v4.y); vd[2] = f2tf(v4.z); vd[3] = f2tf(v4.w);
            }
        }
        __syncthreads();

        // S = q_scaled @ k^T  (warp: 32 rows x 32 keys)
        float sacc[2][4][4];
#pragma unroll
        for (int i = 0; i < 2; i++)
#pragma unroll
            for (int j = 0; j < 4; j++)
#pragma unroll
                for (int e = 0; e < 4; e++) sacc[i][j][e] = 0.f;

#pragma unroll
        for (int ks = 0; ks < 8; ks++) {
            const int k0 = ks * 8;
            unsigned af[2][4];
#pragma unroll
            for (int mi = 0; mi < 2; mi++) {
                const int r = wm + mi * 16 + lr;
                af[mi][0] = __float_as_uint(Qs[r * QS_STR + k0 + lc]);
                af[mi][1] = __float_as_uint(Qs[(r + 8) * QS_STR + k0 + lc]);
                af[mi][2] = __float_as_uint(Qs[r * QS_STR + k0 + 4 + lc]);
                af[mi][3] = __float_as_uint(Qs[(r + 8) * QS_STR + k0 + 4 + lc]);
            }
            unsigned bf[4][2];
#pragma unroll
            for (int ni = 0; ni < 4; ni++) {
                const int r = ni * 8 + lr;
                bf[ni][0] = __float_as_uint(Ks[r * KS_STR + k0 + lc]);
                bf[ni][1] = __float_as_uint(Ks[r * KS_STR + k0 + 4 + lc]);
            }
#pragma unroll
            for (int mi = 0; mi < 2; mi++)
#pragma unroll
                for (int ni = 0; ni < 4; ni++)
                    mma8(sacc[mi][ni][0], sacc[mi][ni][1], sacc[mi][ni][2], sacc[mi][ni][3],
                         af[mi][0], af[mi][1], af[mi][2], af[mi][3],
                         bf[ni][0], bf[ni][1]);
        }

        // relu + rowsum + stage P to smem (per-warp region)
#pragma unroll
        for (int mi = 0; mi < 2; mi++)
#pragma unroll
            for (int ni = 0; ni < 4; ni++) {
                float p0 = fmaxf(sacc[mi][ni][0], 0.f);
                float p1 = fmaxf(sacc[mi][ni][1], 0.f);
                float p2 = fmaxf(sacc[mi][ni][2], 0.f);
                float p3 = fmaxf(sacc[mi][ni][3], 0.f);
                rs[mi][0] += p0 + p1;
                rs[mi][1] += p2 + p3;
                const int rb = mi * 16 + lr;
                const int cb = ni * 8 + (lc << 1);
                *reinterpret_cast<float2*>(Pw + rb * PS_STR + cb)       = make_float2(f2tf(p0), f2tf(p1));
                *reinterpret_cast<float2*>(Pw + (rb + 8) * PS_STR + cb) = make_float2(f2tf(p2), f2tf(p3));
            }
        __syncwarp();

        // ctx += P @ V
#pragma unroll
        for (int ks = 0; ks < 4; ks++) {
            const int k0 = ks * 8;
            unsigned af[2][4];
#pragma unroll
            for (int mi = 0; mi < 2; mi++) {
                const int r = mi * 16 + lr;
                af[mi][0] = __float_as_uint(Pw[r * PS_STR + k0 + lc]);
                af[mi][1] = __float_as_uint(Pw[(r + 8) * PS_STR + k0 + lc]);
                af[mi][2] = __float_as_uint(Pw[r * PS_STR + k0 + 4 + lc]);
                af[mi][3] = __float_as_uint(Pw[(r + 8) * PS_STR + k0 + 4 + lc]);
            }
            unsigned bf[8][2];
#pragma unroll
            for (int ni = 0; ni < 8; ni++) {
                bf[ni][0] = __float_as_uint(Vs[(k0 + lc) * VS_STR + ni * 8 + lr]);
                bf[ni][1] = __float_as_uint(Vs[(k0 + 4 + lc) * VS_STR + ni * 8 + lr]);
            }
#pragma unroll
            for (int mi = 0; mi < 2; mi++)
#pragma unroll
                for (int ni = 0; ni < 8; ni++)
                    mma8(ctx[mi][ni][0], ctx[mi][ni][1], ctx[mi][ni][2], ctx[mi][ni][3],
                         af[mi][0], af[mi][1], af[mi][2], af[mi][3],
                         bf[ni][0], bf[ni][1]);
        }
        __syncthreads();
    }

    // finalize rowsums (reduce across the 4 lanes sharing a row)
    float inv[2][2];
#pragma unroll
    for (int mi = 0; mi < 2; mi++)
#pragma unroll
        for (int hh = 0; hh < 2; hh++) {
            float r = rs[mi][hh];
            r += __shfl_xor_sync(0xffffffffu, r, 1);
            r += __shfl_xor_sync(0xffffffffu, r, 2);
            inv[mi][hh] = 1.f / (r + 1e-6f);
        }

    // write merged ctx [s, h*64 + d]
    const int tb = tbh / NH, h = tbh % NH;
#pragma unroll
    for (int mi = 0; mi < 2; mi++)
#pragma unroll
        for (int ni = 0; ni < 8; ni++)
#pragma unroll
            for (int e = 0; e < 4; e++) {
                const int qrow = qb * 128 + wm + mi * 16 + lr + ((e >> 1) << 3);
                const int s = tb * NSEQ + qrow;
                const int c = h * DHD + ni * 8 + (lc << 1) + (e & 1);
                g_ctx[(size_t)s * DM + c] = ctx[mi][ni][e] * inv[mi][e >> 1];
            }
}

// ---------------------------------------------------------------------------
// Launch
// ---------------------------------------------------------------------------
extern "C" void kernel_launch(void* const* d_in, const int* in_sizes, int n_in,
                              void* d_out, int out_size) {
    const float* x  = (const float*)d_in[0];
    const float* Wq = (const float*)d_in[1];
    const float* bq = (const float*)d_in[2];
    const float* Wk = (const float*)d_in[3];
    const float* bk = (const float*)d_in[4];
    const float* Wv = (const float*)d_in[5];
    const float* bv = (const float*)d_in[6];
    const float* Wo = (const float*)d_in[7];
    const float* bo = (const float*)d_in[8];
    float* out = (float*)d_out;

    (void)in_sizes; (void)n_in; (void)out_size;

    cudaFuncSetAttribute(attn_k, cudaFuncAttributeMaxDynamicSharedMemorySize,
                         (int)(SMEM_F * sizeof(float)));

    dim3 gqkv(NS / 128, DM / 128, 3);
    gemm_qkv_k<<<gqkv, 256>>>(x, Wq, bq, Wk, bk, Wv, bv);

    attn_k<<<dim3(NSEQ / 128, NTB * NH), 128, SMEM_F * sizeof(float)>>>();

    dim3 go(NS / 128, DM / 128);
    gemm_out_k<<<go, 256>>>(Wo, bo, out);
}